// round 5
// baseline (speedup 1.0000x reference)
#include <cuda_runtime.h>
#include <cstdint>
#include <math.h>

#define NB   4
#define S    2048
#define D    1024
#define NS   (NB*S)               // 8192

// ---------------- device scratch (no allocs allowed) ----------------
__device__ float g_wq [(size_t)NS*D];     // 32 MB  q @ WQ^T
__device__ float g_wk [(size_t)NS*D];     // 32 MB  k @ WK^T
__device__ float g_wvt[(size_t)D*NS];     // 32 MB  (WV @ v^T): [o][n*S+s]
__device__ float g_p  [(size_t)NB*S*S];   // 64 MB  scores P[n][k][q]
__device__ float g_pt [(size_t)NB*S*S];   // 64 MB  softmaxed P transposed [n][q][k]

// ---------------- helpers ----------------
__device__ __forceinline__ uint32_t f2tf32(float f) {
    uint32_t r;
    asm("cvt.rna.tf32.f32 %0, %1;" : "=r"(r) : "f"(f));
    return r;
}
__device__ __forceinline__ void mma_tf32(float* c, const uint32_t* a, const uint32_t* b) {
    asm volatile(
        "mma.sync.aligned.m16n8k8.row.col.f32.tf32.tf32.f32 "
        "{%0,%1,%2,%3}, {%4,%5,%6,%7}, {%8,%9}, {%0,%1,%2,%3};"
        : "+f"(c[0]), "+f"(c[1]), "+f"(c[2]), "+f"(c[3])
        : "r"(a[0]), "r"(a[1]), "r"(a[2]), "r"(a[3]), "r"(b[0]), "r"(b[1]));
}
__device__ __forceinline__ void cp_async16(uint32_t dst, const void* src) {
    asm volatile("cp.async.cg.shared.global [%0], [%1], 16;\n" :: "r"(dst), "l"(src));
}
__device__ __forceinline__ uint32_t smem_u32(const void* p) {
    uint32_t a;
    asm("{ .reg .u64 t; cvta.to.shared.u64 t, %1; cvt.u32.u64 %0, t; }" : "=r"(a) : "l"(p));
    return a;
}

// ---------------- 2-term-split TF32 NT GEMM with chunk-drained accumulation ---
// C[m,n] = sum_k A[m,k] * B[n,k]  (fp32 in/out)
// Products {00, 10, 01}; per-BK chunk accumulators drained into fp32 master
// with RNE adds to suppress the tensor-core RZ accumulation bias.
#define BM   128
#define BN   128
#define BKF  32
#define ROWF 36
#define TILEF (128*ROWF)
#define SMEM_BYTES (4*TILEF*4)     // 73728 B

__global__ __launch_bounds__(256, 1) void gemm3t(
    const float* __restrict__ A, long long batchA, int lda,
    const float* __restrict__ B, long long batchB, int ldb,
    float* __restrict__ C, long long batchC, int ldc,
    int K)
{
    extern __shared__ float smf[];
    float* const bufA[2] = { smf,         smf + 2 * TILEF };
    float* const bufB[2] = { smf + TILEF, smf + 3 * TILEF };

    const int tid  = threadIdx.x;
    const int wid  = tid >> 5;
    const int lane = tid & 31;
    const int gid  = lane >> 2;
    const int t4   = lane & 3;
    const int m_w  = (wid & 1) * 64;
    const int n_w  = (wid >> 1) * 32;
    const int bm   = blockIdx.y * BM;
    const int bn   = blockIdx.x * BN;

    const float* Ab = A + (long long)blockIdx.z * batchA;
    const float* Bb = B + (long long)blockIdx.z * batchB;
    float*       Cb = C + (long long)blockIdx.z * batchC;

    auto load_tile = [&](int kt, int st) {
        const int k0 = kt * BKF;
        const uint32_t da = smem_u32(bufA[st]);
        const uint32_t db = smem_u32(bufB[st]);
        #pragma unroll
        for (int i = 0; i < 4; ++i) {
            int c = tid + (i << 8);
            int r = c >> 3;
            int j = (c & 7) << 2;
            cp_async16(da + (r * ROWF + j) * 4, Ab + (size_t)(bm + r) * lda + k0 + j);
            cp_async16(db + (r * ROWF + j) * 4, Bb + (size_t)(bn + r) * ldb + k0 + j);
        }
        asm volatile("cp.async.commit_group;\n" ::: "memory");
    };

    float acc_hi[4][4][4] = {};       // master accumulator (RNE adds)
    float acc[4][4][4] = {};          // per-chunk MMA accumulator
    const int NK = K / BKF;

    load_tile(0, 0);

    for (int kt = 0; kt < NK; ++kt) {
        if (kt + 1 < NK) {
            load_tile(kt + 1, (kt + 1) & 1);
            asm volatile("cp.async.wait_group 1;\n" ::: "memory");
        } else {
            asm volatile("cp.async.wait_group 0;\n" ::: "memory");
        }
        __syncthreads();

        const float* As = bufA[kt & 1];
        const float* Bs = bufB[kt & 1];

        #pragma unroll
        for (int kk = 0; kk < BKF; kk += 8) {
            uint32_t a0[4][4], a1[4][4];
            #pragma unroll
            for (int am = 0; am < 4; ++am) {
                const int r0 = m_w + am * 16 + gid;
                float f[4] = { As[(r0    ) * ROWF + kk + t4],
                               As[(r0 + 8) * ROWF + kk + t4],
                               As[(r0    ) * ROWF + kk + t4 + 4],
                               As[(r0 + 8) * ROWF + kk + t4 + 4] };
                #pragma unroll
                for (int i = 0; i < 4; ++i) {
                    a0[am][i] = f2tf32(f[i]);
                    a1[am][i] = f2tf32(f[i] - __uint_as_float(a0[am][i]));
                }
            }
            uint32_t b0[4][2], b1[4][2];
            #pragma unroll
            for (int an = 0; an < 4; ++an) {
                const int c0 = n_w + an * 8 + gid;
                float f[2] = { Bs[c0 * ROWF + kk + t4],
                               Bs[c0 * ROWF + kk + t4 + 4] };
                #pragma unroll
                for (int i = 0; i < 2; ++i) {
                    b0[an][i] = f2tf32(f[i]);
                    b1[an][i] = f2tf32(f[i] - __uint_as_float(b0[an][i]));
                }
            }
            #pragma unroll
            for (int am = 0; am < 4; ++am)
                #pragma unroll
                for (int an = 0; an < 4; ++an) {
                    mma_tf32(acc[am][an], a0[am], b0[an]);
                    mma_tf32(acc[am][an], a1[am], b0[an]);
                    mma_tf32(acc[am][an], a0[am], b1[an]);
                }
        }

        // drain chunk accumulator into master with RNE adds (kills RZ bias)
        #pragma unroll
        for (int am = 0; am < 4; ++am)
            #pragma unroll
            for (int an = 0; an < 4; ++an)
                #pragma unroll
                for (int i = 0; i < 4; ++i) {
                    acc_hi[am][an][i] += acc[am][an][i];
                    acc[am][an][i] = 0.f;
                }

        __syncthreads();
    }

    #pragma unroll
    for (int am = 0; am < 4; ++am) {
        const int r0 = bm + m_w + am * 16 + gid;
        #pragma unroll
        for (int an = 0; an < 4; ++an) {
            const int cc = bn + n_w + an * 8 + 2 * t4;
            *(float2*)&Cb[(size_t)(r0    ) * ldc + cc] = make_float2(acc_hi[am][an][0], acc_hi[am][an][1]);
            *(float2*)&Cb[(size_t)(r0 + 8) * ldc + cc] = make_float2(acc_hi[am][an][2], acc_hi[am][an][3]);
        }
    }
}

// ---------------- softmax over q (rows of P[n][k][:]) + /D ----------------
__global__ __launch_bounds__(256) void softmax_div(float* __restrict__ P)
{
    float* p = P + (size_t)blockIdx.x * S;
    const int tid  = threadIdx.x;
    const int lane = tid & 31;
    const int wid  = tid >> 5;

    float v[8];
    float mx = -3.4e38f;
    #pragma unroll
    for (int i = 0; i < 8; ++i) { v[i] = p[tid + (i << 8)]; mx = fmaxf(mx, v[i]); }
    #pragma unroll
    for (int o = 16; o > 0; o >>= 1) mx = fmaxf(mx, __shfl_xor_sync(0xffffffffu, mx, o));

    __shared__ float smax[8], ssum[8];
    if (lane == 0) smax[wid] = mx;
    __syncthreads();
    mx = smax[0];
    #pragma unroll
    for (int w = 1; w < 8; ++w) mx = fmaxf(mx, smax[w]);

    float s = 0.f;
    #pragma unroll
    for (int i = 0; i < 8; ++i) { v[i] = expf(v[i] - mx); s += v[i]; }
    #pragma unroll
    for (int o = 16; o > 0; o >>= 1) s += __shfl_xor_sync(0xffffffffu, s, o);
    if (lane == 0) ssum[wid] = s;
    __syncthreads();
    s = ssum[0];
    #pragma unroll
    for (int w = 1; w < 8; ++w) s += ssum[w];

    const float inv = 1.0f / (s * (float)D);
    #pragma unroll
    for (int i = 0; i < 8; ++i) p[tid + (i << 8)] = v[i] * inv;
}

// ---------------- transpose P[n][k][q] -> Pt[n][q][k] ----------------
__global__ __launch_bounds__(256) void transpose_f(const float* __restrict__ P,
                                                   float* __restrict__ Pt)
{
    __shared__ float ts[32][33];
    const int z  = blockIdx.z;
    const int qb = blockIdx.x * 32;
    const int kb = blockIdx.y * 32;
    const int tx = threadIdx.x;
    const int ty = threadIdx.y;
    const float* p = P  + (size_t)z * S * S;
    float*       o = Pt + (size_t)z * S * S;

    #pragma unroll
    for (int i = 0; i < 4; ++i)
        ts[ty + i * 8][tx] = p[(size_t)(kb + ty + i * 8) * S + qb + tx];
    __syncthreads();
    #pragma unroll
    for (int i = 0; i < 4; ++i)
        o[(size_t)(qb + ty + i * 8) * S + kb + tx] = ts[tx][ty + i * 8];
}

// ---------------- launch ----------------
extern "C" void kernel_launch(void* const* d_in, const int* in_sizes, int n_in,
                              void* d_out, int out_size)
{
    (void)in_sizes; (void)n_in; (void)out_size;
    const float* v  = (const float*)d_in[0];
    const float* k  = (const float*)d_in[1];
    const float* q  = (const float*)d_in[2];
    const float* WV = (const float*)d_in[3];
    const float* WQ = (const float*)d_in[4];
    const float* WK = (const float*)d_in[5];
    float* out = (float*)d_out;

    float *wq, *wk, *wvt, *p, *pt;
    cudaGetSymbolAddress((void**)&wq,  g_wq);
    cudaGetSymbolAddress((void**)&wk,  g_wk);
    cudaGetSymbolAddress((void**)&wvt, g_wvt);
    cudaGetSymbolAddress((void**)&p,   g_p);
    cudaGetSymbolAddress((void**)&pt,  g_pt);

    cudaFuncSetAttribute(gemm3t, cudaFuncAttributeMaxDynamicSharedMemorySize, SMEM_BYTES);

    const dim3 blk(256);

    // wq = q @ WQ^T   [NS, D]
    gemm3t<<<dim3(D / BN, NS / BM, 1), blk, SMEM_BYTES>>>(q, 0, D, WQ, 0, D, wq, 0, D, D);
    // wk = k @ WK^T   [NS, D]
    gemm3t<<<dim3(D / BN, NS / BM, 1), blk, SMEM_BYTES>>>(k, 0, D, WK, 0, D, wk, 0, D, D);
    // wvT = WV @ v^T  [D, NS]
    gemm3t<<<dim3(NS / BN, D / BM, 1), blk, SMEM_BYTES>>>(WV, 0, D, v, 0, D, wvt, 0, NS, D);
    // scores P[n][k][q] = wk @ wq^T per batch  [S, S]
    gemm3t<<<dim3(S / BN, S / BM, NB), blk, SMEM_BYTES>>>(
        wk, (long long)S * D, D, wq, (long long)S * D, D, p, (long long)S * S, S, D);
    // softmax over q (rows) + /D
    softmax_div<<<NB * S, 256>>>(p);
    // transpose: Pt[n][q][k]
    transpose_f<<<dim3(S / 32, S / 32, NB), dim3(32, 8)>>>(p, pt);
    // out[n][q][o] = Pt @ wvT^T per batch  [S, D], K = S
    gemm3t<<<dim3(D / BN, S / BM, NB), blk, SMEM_BYTES>>>(
        pt, (long long)S * S, S, wvt, (long long)S, NS, out, (long long)S * D, D, S);
}